// round 2
// baseline (speedup 1.0000x reference)
#include <cuda_runtime.h>
#include <utility>
#include <cstddef>

// ---------------------------------------------------------------------------
// Compile-time Clifford algebra G(3,0,1) tables (same algorithm as reference)
// Blade order: by grade then lex: 1,e0,e1,e2,e3,e01,e02,e03,e12,e13,e23,
//              e012,e013,e023,e123,e0123.  bit0=e0 (degenerate), bits1..3=e1..3
// ---------------------------------------------------------------------------
namespace ga {

constexpr int MASK[16]  = {0,1,2,4,8,3,5,9,6,10,12,7,11,13,14,15};
constexpr int GRADE[16] = {0,1,1,1,1,2,2,2,2,2,2,3,3,3,3,4};

constexpr int mask_to_idx(int m) {
    int r = 0;
    for (int i = 0; i < 16; i++) if (MASK[i] == m) r = i;
    return r;
}

// # of transpositions to interleave-sort generators of a then b
constexpr int swaps(int a, int b) {
    int s = 0;
    for (int q = 0; q < 4; q++)
        if ((b >> q) & 1)
            for (int p = q + 1; p < 4; p++)
                if ((a >> p) & 1) s++;
    return s;
}
constexpr float rsign(int a, int b) { return (swaps(a, b) & 1) ? -1.0f : 1.0f; }

struct Tab { float s[16][16]; int k[16][16]; };

// geometric product: sign = reorder sign * metric over common bits (e0^2=0)
constexpr Tab make_gp() {
    Tab t{};
    for (int i = 0; i < 16; i++)
        for (int j = 0; j < 16; j++) {
            int a = MASK[i], b = MASK[j];
            float sg = rsign(a, b);
            if (a & b & 1) sg = 0.0f;   // e0 squared -> 0
            t.s[i][j] = sg;
            t.k[i][j] = mask_to_idx(a ^ b);
        }
    return t;
}

// dual(e_i) = dsign(i) * e_complement(i)  (metric-free right complement)
constexpr float dsign(int i) { return rsign(MASK[i], 15 ^ MASK[i]); }

// join(x,y) = undual(dual(x) ^ dual(y))
constexpr Tab make_join() {
    Tab t{};
    for (int i = 0; i < 16; i++)
        for (int j = 0; j < 16; j++) {
            int ci = 15 ^ MASK[i], cj = 15 ^ MASK[j];
            if (ci & cj) { t.s[i][j] = 0.0f; t.k[i][j] = 0; }
            else {
                int m = ci | cj;
                int p = mask_to_idx(15 ^ m);           // undual target blade
                t.s[i][j] = dsign(i) * dsign(j) * rsign(ci, cj) * dsign(p);
                t.k[i][j] = p;
            }
        }
    return t;
}

constexpr Tab GP = make_gp();
constexpr Tab JN = make_join();

} // namespace ga

// ---------------------------------------------------------------------------
// Static-for helpers. Every table access is routed through a constexpr local
// so all array indices are compile-time constants (keeps locals in registers
// and satisfies nvcc's host-constexpr-in-device-code rules).
// ---------------------------------------------------------------------------
template<int I, int J>
__device__ __forceinline__ void gp_term(float* p, const float* a, const float* b) {
    constexpr float s = ga::GP.s[I][J];
    constexpr int   k = ga::GP.k[I][J];
    if constexpr (s != 0.0f) p[k] += s * a[I] * b[J];
}
template<int I, int... Js>
__device__ __forceinline__ void gp_row(float* p, const float* a, const float* b,
                                       std::integer_sequence<int, Js...>) {
    (gp_term<I, Js>(p, a, b), ...);
}
template<int... Is>
__device__ __forceinline__ void gp_mat(float* p, const float* a, const float* b,
                                       std::integer_sequence<int, Is...>) {
    (gp_row<Is>(p, a, b, std::make_integer_sequence<int, 16>{}), ...);
}

template<int I, int J>
__device__ __forceinline__ void jn_term(float* p, const float* a, const float* b) {
    constexpr float s = ga::JN.s[I][J];
    constexpr int   k = ga::JN.k[I][J];
    if constexpr (s != 0.0f) p[k] += s * a[I] * b[J];
}
template<int I, int... Js>
__device__ __forceinline__ void jn_row(float* p, const float* a, const float* b,
                                       std::integer_sequence<int, Js...>) {
    (jn_term<I, Js>(p, a, b), ...);
}
template<int... Is>
__device__ __forceinline__ void jn_mat(float* p, const float* a, const float* b,
                                       std::integer_sequence<int, Is...>) {
    (jn_row<Is>(p, a, b, std::make_integer_sequence<int, 16>{}), ...);
}

template<int K>
__device__ __forceinline__ void proj_k(float* aPX, float* aPY, float* aJX, float* aJY,
                                       const float* xk, const float4* wg) {
    constexpr int G = ga::GRADE[K];     // forced compile-time evaluation
    aPX[K] += xk[K] * wg[G].x;
    aPY[K] += xk[K] * wg[G].y;
    aJX[K] += xk[K] * wg[G].z;
    aJY[K] += xk[K] * wg[G].w;
}
template<int... Ks>
__device__ __forceinline__ void proj_fma(float* aPX, float* aPY, float* aJX, float* aJY,
                                         const float* xk, const float4* wg,
                                         std::integer_sequence<int, Ks...>) {
    (proj_k<Ks>(aPX, aPY, aJX, aJY, xk, wg), ...);
}

template<int K>
__device__ __forceinline__ void final_k(float* a1, float* a2,
                                        const float* fk, const float2* ug) {
    constexpr int G = ga::GRADE[K];     // forced compile-time evaluation
    a1[K] += fk[K] * ug[G].x;
    a2[K] += fk[K] * ug[G].y;
}
template<int... Ks>
__device__ __forceinline__ void final_fma(float* a1, float* a2,
                                          const float* fk, const float2* ug,
                                          std::integer_sequence<int, Ks...>) {
    (final_k<Ks>(a1, a2, fk, ug), ...);
}

// ---------------------------------------------------------------------------
// Problem constants: B=32, N=1024, Cin=64, Cout=64, H=32  -> 32768 tokens
// ---------------------------------------------------------------------------
static constexpr int TOKENS   = 32 * 1024;
static constexpr int WARPS_PB = 8;          // tokens per block
static constexpr int THREADS  = WARPS_PB * 32;
static constexpr int NBLOCKS  = TOKENS / WARPS_PB;

// Transposed weight scratch (static __device__ -> no allocation)
// WP4: [5 grades][64 i][32 c][4 tensors: prodX,prodY,joinX,joinY]
// WF2: [5 grades][64 cc][32 o][2: o, o+32]
__device__ float g_WP4[5 * 64 * 32 * 4];
__device__ float g_WF2[5 * 64 * 32 * 2];

__global__ void prep_kernel(const float* __restrict__ wpx, const float* __restrict__ wpy,
                            const float* __restrict__ wjx, const float* __restrict__ wjy,
                            const float* __restrict__ wf) {
    int idx = blockIdx.x * blockDim.x + threadIdx.x;     // over 5*64*32 = 10240
    if (idx < 5 * 64 * 32) {
        int c = idx & 31;            // lane channel (c for proj, o for final)
        int i = (idx >> 5) & 63;     // reduction index (i for proj, cc for final)
        int g = idx >> 11;           // grade
        int src = (g * 32 + c) * 64 + i;   // raw layout [5][32][64]
        g_WP4[idx * 4 + 0] = wpx[src];
        g_WP4[idx * 4 + 1] = wpy[src];
        g_WP4[idx * 4 + 2] = wjx[src];
        g_WP4[idx * 4 + 3] = wjy[src];
        // final weights raw layout [5][64 o][64 cc]
        g_WF2[idx * 2 + 0] = wf[(g * 64 + c)      * 64 + i];
        g_WF2[idx * 2 + 1] = wf[(g * 64 + c + 32) * 64 + i];
    }
}

// Shared layout (dynamic):
//   [0 .. 8*1024)            per-warp token buffer: x tile, later feats
//   [8*1024 .. 8*1024+40960) weight buffer: WP4 during phase A, WF2 for phase C
static constexpr int SMEM_FLOATS = WARPS_PB * 1024 + 5 * 64 * 32 * 4;
static constexpr int SMEM_BYTES  = SMEM_FLOATS * 4;   // 196608

__global__ __launch_bounds__(THREADS, 1)
void gbl_kernel(const float* __restrict__ x, const float* __restrict__ ref,
                float* __restrict__ out) {
    extern __shared__ float smem[];
    float* tb   = smem;                    // [WARPS_PB][1024]
    float* wbuf = smem + WARPS_PB * 1024;  // 40960 floats

    const int tid  = threadIdx.x;
    const int w    = tid >> 5;
    const int lane = tid & 31;
    const int tok  = blockIdx.x * WARPS_PB + w;

    // ---- stage projection weights into shared (cooperative, coalesced) ----
    {
        float4*       d = reinterpret_cast<float4*>(wbuf);
        const float4* s = reinterpret_cast<const float4*>(g_WP4);
        for (int i = tid; i < 5 * 64 * 32; i += THREADS) d[i] = s[i];
    }
    // ---- stage this warp's x tile (4KB contiguous) ----
    {
        const float4* xs  = reinterpret_cast<const float4*>(x + (size_t)tok * 1024);
        float4*       tb4 = reinterpret_cast<float4*>(tb + w * 1024);
        #pragma unroll
        for (int r = 0; r < 8; r++) tb4[r * 32 + lane] = xs[r * 32 + lane];
    }
    __syncthreads();

    // ---- Phase A: four equivariant projections, lane = channel c ----
    float aPX[16] = {}, aPY[16] = {}, aJX[16] = {}, aJY[16] = {};
    {
        const float4* tb4 = reinterpret_cast<const float4*>(tb + w * 1024);
        const float4* W4  = reinterpret_cast<const float4*>(wbuf);
        #pragma unroll 2
        for (int i = 0; i < 64; i++) {
            float4 xa = tb4[i * 4 + 0];
            float4 xb = tb4[i * 4 + 1];
            float4 xc = tb4[i * 4 + 2];
            float4 xd = tb4[i * 4 + 3];
            float xk[16] = {xa.x, xa.y, xa.z, xa.w, xb.x, xb.y, xb.z, xb.w,
                            xc.x, xc.y, xc.z, xc.w, xd.x, xd.y, xd.z, xd.w};
            float4 wg[5];
            #pragma unroll
            for (int g = 0; g < 5; g++) wg[g] = W4[(g * 64 + i) * 32 + lane];
            proj_fma(aPX, aPY, aJX, aJY, xk, wg, std::make_integer_sequence<int, 16>{});
        }
    }

    // scale join-X by reference pseudoscalar coefficient
    {
        float r15 = __ldg(ref + (size_t)tok * 16 + 15);
        #pragma unroll
        for (int k = 0; k < 16; k++) aJX[k] *= r15;
    }

    // ---- Phase B: sparse Clifford bilinears (all in registers) ----
    float prod[16] = {}, jn[16] = {};
    gp_mat(prod, aPX, aPY, std::make_integer_sequence<int, 16>{});
    jn_mat(jn,   aJX, aJY, std::make_integer_sequence<int, 16>{});

    // write feats over the consumed x tile: layout float4 [kq=4][c=64]
    __syncwarp();
    {
        float4* fb = reinterpret_cast<float4*>(tb + w * 1024);
        #pragma unroll
        for (int kq = 0; kq < 4; kq++) {
            fb[kq * 64 + lane]      = make_float4(prod[kq*4], prod[kq*4+1], prod[kq*4+2], prod[kq*4+3]);
            fb[kq * 64 + 32 + lane] = make_float4(jn[kq*4],   jn[kq*4+1],   jn[kq*4+2],   jn[kq*4+3]);
        }
    }
    __syncthreads();   // all warps done with WP4 in wbuf

    // ---- swap in final weights ----
    {
        float4*       d = reinterpret_cast<float4*>(wbuf);
        const float4* s = reinterpret_cast<const float4*>(g_WF2);
        for (int i = tid; i < 5 * 64 * 32 / 2; i += THREADS) d[i] = s[i];
    }
    __syncthreads();

    // ---- Phase C: final equivariant projection, lane = o (and o+32) ----
    float aO[16] = {}, aO2[16] = {};
    {
        const float4* fb = reinterpret_cast<const float4*>(tb + w * 1024);
        const float2* WF = reinterpret_cast<const float2*>(wbuf);
        #pragma unroll 2
        for (int cc = 0; cc < 64; cc++) {
            float4 f0 = fb[0 * 64 + cc];
            float4 f1 = fb[1 * 64 + cc];
            float4 f2 = fb[2 * 64 + cc];
            float4 f3 = fb[3 * 64 + cc];
            float fk[16] = {f0.x, f0.y, f0.z, f0.w, f1.x, f1.y, f1.z, f1.w,
                            f2.x, f2.y, f2.z, f2.w, f3.x, f3.y, f3.z, f3.w};
            float2 ug[5];
            #pragma unroll
            for (int g = 0; g < 5; g++) ug[g] = WF[(g * 64 + cc) * 32 + lane];
            final_fma(aO, aO2, fk, ug, std::make_integer_sequence<int, 16>{});
        }
    }

    // ---- store: out[tok][o][k], float4 over k ----
    {
        float4* op = reinterpret_cast<float4*>(out + (size_t)tok * 1024);
        #pragma unroll
        for (int kq = 0; kq < 4; kq++) {
            op[lane * 4 + kq]        = make_float4(aO[kq*4],  aO[kq*4+1],  aO[kq*4+2],  aO[kq*4+3]);
            op[(lane + 32) * 4 + kq] = make_float4(aO2[kq*4], aO2[kq*4+1], aO2[kq*4+2], aO2[kq*4+3]);
        }
    }
}

// ---------------------------------------------------------------------------
// Launch
// ---------------------------------------------------------------------------
extern "C" void kernel_launch(void* const* d_in, const int* in_sizes, int n_in,
                              void* d_out, int out_size) {
    const float* x   = (const float*)d_in[0];
    const float* ref = (const float*)d_in[1];
    const float* wpx = (const float*)d_in[2];
    const float* wpy = (const float*)d_in[3];
    const float* wjx = (const float*)d_in[4];
    const float* wjy = (const float*)d_in[5];
    const float* wf  = (const float*)d_in[6];
    float* out = (float*)d_out;

    prep_kernel<<<40, 256>>>(wpx, wpy, wjx, wjy, wf);

    cudaFuncSetAttribute(gbl_kernel, cudaFuncAttributeMaxDynamicSharedMemorySize, SMEM_BYTES);
    gbl_kernel<<<NBLOCKS, THREADS, SMEM_BYTES>>>(x, ref, out);
}

// round 3
// speedup vs baseline: 1.1257x; 1.1257x over previous
#include <cuda_runtime.h>
#include <utility>
#include <cstddef>

// ---------------------------------------------------------------------------
// Compile-time Clifford algebra G(3,0,1) tables (same algorithm as reference)
// Blade order: 1,e0,e1,e2,e3,e01,e02,e03,e12,e13,e23,e012,e013,e023,e123,e0123
// bit0 = e0 (degenerate), bits1..3 = e1..e3
// ---------------------------------------------------------------------------
namespace ga {

constexpr int MASK[16]  = {0,1,2,4,8,3,5,9,6,10,12,7,11,13,14,15};
constexpr int GRADE[16] = {0,1,1,1,1,2,2,2,2,2,2,3,3,3,3,4};

constexpr int mask_to_idx(int m) {
    int r = 0;
    for (int i = 0; i < 16; i++) if (MASK[i] == m) r = i;
    return r;
}

constexpr int swaps(int a, int b) {
    int s = 0;
    for (int q = 0; q < 4; q++)
        if ((b >> q) & 1)
            for (int p = q + 1; p < 4; p++)
                if ((a >> p) & 1) s++;
    return s;
}
constexpr float rsign(int a, int b) { return (swaps(a, b) & 1) ? -1.0f : 1.0f; }

struct Tab { float s[16][16]; int k[16][16]; };

constexpr Tab make_gp() {
    Tab t{};
    for (int i = 0; i < 16; i++)
        for (int j = 0; j < 16; j++) {
            int a = MASK[i], b = MASK[j];
            float sg = rsign(a, b);
            if (a & b & 1) sg = 0.0f;   // e0^2 = 0
            t.s[i][j] = sg;
            t.k[i][j] = mask_to_idx(a ^ b);
        }
    return t;
}

constexpr float dsign(int i) { return rsign(MASK[i], 15 ^ MASK[i]); }

constexpr Tab make_join() {
    Tab t{};
    for (int i = 0; i < 16; i++)
        for (int j = 0; j < 16; j++) {
            int ci = 15 ^ MASK[i], cj = 15 ^ MASK[j];
            if (ci & cj) { t.s[i][j] = 0.0f; t.k[i][j] = 0; }
            else {
                int m = ci | cj;
                int p = mask_to_idx(15 ^ m);
                t.s[i][j] = dsign(i) * dsign(j) * rsign(ci, cj) * dsign(p);
                t.k[i][j] = p;
            }
        }
    return t;
}

constexpr Tab GP = make_gp();
constexpr Tab JN = make_join();

} // namespace ga

// ---------------------------------------------------------------------------
// Static-for helpers: all indices compile-time so locals stay in registers
// ---------------------------------------------------------------------------
template<int I, int J>
__device__ __forceinline__ void gp_term(float* p, const float* a, const float* b) {
    constexpr float s = ga::GP.s[I][J];
    constexpr int   k = ga::GP.k[I][J];
    if constexpr (s != 0.0f) p[k] += s * a[I] * b[J];
}
template<int I, int... Js>
__device__ __forceinline__ void gp_row(float* p, const float* a, const float* b,
                                       std::integer_sequence<int, Js...>) {
    (gp_term<I, Js>(p, a, b), ...);
}
template<int... Is>
__device__ __forceinline__ void gp_mat(float* p, const float* a, const float* b,
                                       std::integer_sequence<int, Is...>) {
    (gp_row<Is>(p, a, b, std::make_integer_sequence<int, 16>{}), ...);
}

template<int I, int J>
__device__ __forceinline__ void jn_term(float* p, const float* a, const float* b) {
    constexpr float s = ga::JN.s[I][J];
    constexpr int   k = ga::JN.k[I][J];
    if constexpr (s != 0.0f) p[k] += s * a[I] * b[J];
}
template<int I, int... Js>
__device__ __forceinline__ void jn_row(float* p, const float* a, const float* b,
                                       std::integer_sequence<int, Js...>) {
    (jn_term<I, Js>(p, a, b), ...);
}
template<int... Is>
__device__ __forceinline__ void jn_mat(float* p, const float* a, const float* b,
                                       std::integer_sequence<int, Is...>) {
    (jn_row<Is>(p, a, b, std::make_integer_sequence<int, 16>{}), ...);
}

// pair FMA: two output tensors sharing one float2 weight per grade
template<int K>
__device__ __forceinline__ void pair_k(float* aX, float* aY, const float* xk, const float2* wg) {
    constexpr int G = ga::GRADE[K];
    aX[K] += xk[K] * wg[G].x;
    aY[K] += xk[K] * wg[G].y;
}
template<int... Ks>
__device__ __forceinline__ void pair_fma(float* aX, float* aY, const float* xk, const float2* wg,
                                         std::integer_sequence<int, Ks...>) {
    (pair_k<Ks>(aX, aY, xk, wg), ...);
}

// ---------------------------------------------------------------------------
// Problem constants: B=32, N=1024, Cin=64, Cout=64, H=32 -> 32768 tokens
// ---------------------------------------------------------------------------
static constexpr int TOKENS   = 32 * 1024;
static constexpr int WARPS_PB = 8;
static constexpr int TPW      = 2;                    // tokens per warp
static constexpr int TOK_PB   = WARPS_PB * TPW;       // 16 tokens per block
static constexpr int THREADS  = WARPS_PB * 32;
static constexpr int NBLOCKS  = TOKENS / TOK_PB;      // 2048

// Transposed weight scratch (static __device__ -> no allocation)
// WPa: [5 g][64 i][32 c] float2 (prodX, prodY)
// WPb: [5 g][64 i][32 c] float2 (joinX, joinY)
// WF2: [5 g][64 cc][32 o] float2 (o, o+32)
__device__ float g_WPa[5 * 64 * 32 * 2];
__device__ float g_WPb[5 * 64 * 32 * 2];
__device__ float g_WF2[5 * 64 * 32 * 2];

__global__ void prep_kernel(const float* __restrict__ wpx, const float* __restrict__ wpy,
                            const float* __restrict__ wjx, const float* __restrict__ wjy,
                            const float* __restrict__ wf) {
    int idx = blockIdx.x * blockDim.x + threadIdx.x;     // over 5*64*32 = 10240
    if (idx < 5 * 64 * 32) {
        int c = idx & 31;            // lane channel
        int i = (idx >> 5) & 63;     // reduction index
        int g = idx >> 11;           // grade
        int src = (g * 32 + c) * 64 + i;     // proj weights raw layout [5][32][64]
        g_WPa[idx * 2 + 0] = wpx[src];
        g_WPa[idx * 2 + 1] = wpy[src];
        g_WPb[idx * 2 + 0] = wjx[src];
        g_WPb[idx * 2 + 1] = wjy[src];
        // final weights raw layout [5][64 o][64 cc]
        g_WF2[idx * 2 + 0] = wf[(g * 64 + c)      * 64 + i];
        g_WF2[idx * 2 + 1] = wf[(g * 64 + c + 32) * 64 + i];
    }
}

// Shared layout:
//   tb:   [16 token slots][1024 floats]  (x tile, later feats)   65536 B
//   wbuf: WPa+WPb (40960 floats) during phase A; WF2 (20480) for phase C  163840 B
static constexpr int TB_FLOATS   = TOK_PB * 1024;          // 16384
static constexpr int WBUF_FLOATS = 5 * 64 * 32 * 2 * 2;    // 40960
static constexpr int SMEM_BYTES  = (TB_FLOATS + WBUF_FLOATS) * 4;  // 229376

// one projection pass: 2 tensors x 2 tokens, weights amortized across tokens
__device__ __forceinline__ void run_pass(const float2* __restrict__ W, int lane,
                                         const float* __restrict__ t0,
                                         const float* __restrict__ t1,
                                         float aX0[16], float aY0[16],
                                         float aX1[16], float aY1[16]) {
    #pragma unroll 2
    for (int i = 0; i < 64; i++) {
        float2 wg[5];
        #pragma unroll
        for (int g = 0; g < 5; g++) wg[g] = W[(g * 64 + i) * 32 + lane];

        {
            const float4* xp = reinterpret_cast<const float4*>(t0 + i * 16);
            float4 a = xp[0], b = xp[1], c = xp[2], d = xp[3];
            float xk[16] = {a.x,a.y,a.z,a.w, b.x,b.y,b.z,b.w,
                            c.x,c.y,c.z,c.w, d.x,d.y,d.z,d.w};
            pair_fma(aX0, aY0, xk, wg, std::make_integer_sequence<int, 16>{});
        }
        {
            const float4* xp = reinterpret_cast<const float4*>(t1 + i * 16);
            float4 a = xp[0], b = xp[1], c = xp[2], d = xp[3];
            float xk[16] = {a.x,a.y,a.z,a.w, b.x,b.y,b.z,b.w,
                            c.x,c.y,c.z,c.w, d.x,d.y,d.z,d.w};
            pair_fma(aX1, aY1, xk, wg, std::make_integer_sequence<int, 16>{});
        }
    }
}

__global__ __launch_bounds__(THREADS, 1)
void gbl_kernel(const float* __restrict__ x, const float* __restrict__ ref,
                float* __restrict__ out) {
    extern __shared__ float smem[];
    float* tb   = smem;                 // [TOK_PB][1024]
    float* wbuf = smem + TB_FLOATS;

    const int tid  = threadIdx.x;
    const int w    = tid >> 5;
    const int lane = tid & 31;
    const int s0   = w * 2;                       // token slots for this warp
    const int tok0 = blockIdx.x * TOK_PB + s0;

    // ---- stage projection weights (WPa | WPb) into shared ----
    {
        float4*       d = reinterpret_cast<float4*>(wbuf);
        const float4* a = reinterpret_cast<const float4*>(g_WPa);
        const float4* b = reinterpret_cast<const float4*>(g_WPb);
        constexpr int QA = 5 * 64 * 32 * 2 / 4;   // 10240 float4 per table
        for (int i = tid; i < QA; i += THREADS) { d[i] = a[i]; d[QA + i] = b[i]; }
    }
    // ---- stage this warp's 2 token tiles (8KB contiguous in gmem) ----
    {
        const float4* xs  = reinterpret_cast<const float4*>(x + (size_t)tok0 * 1024);
        float4*       tb4 = reinterpret_cast<float4*>(tb + s0 * 1024);
        #pragma unroll
        for (int r = 0; r < 16; r++) tb4[r * 32 + lane] = xs[r * 32 + lane];
    }
    __syncthreads();

    const float* t0 = tb + s0 * 1024;
    const float* t1 = tb + (s0 + 1) * 1024;
    const float2* WPa = reinterpret_cast<const float2*>(wbuf);
    const float2* WPb = WPa + 5 * 64 * 32;

    // ---- Pass 1: prodX / prodY projections, then geometric product ----
    float prod0[16] = {}, prod1[16] = {};
    {
        float aX0[16] = {}, aY0[16] = {}, aX1[16] = {}, aY1[16] = {};
        run_pass(WPa, lane, t0, t1, aX0, aY0, aX1, aY1);
        gp_mat(prod0, aX0, aY0, std::make_integer_sequence<int, 16>{});
        gp_mat(prod1, aX1, aY1, std::make_integer_sequence<int, 16>{});
    }

    // ---- Pass 2: joinX / joinY projections, scale, join product ----
    float jn0[16] = {}, jn1[16] = {};
    {
        float aX0[16] = {}, aY0[16] = {}, aX1[16] = {}, aY1[16] = {};
        run_pass(WPb, lane, t0, t1, aX0, aY0, aX1, aY1);
        float r0 = __ldg(ref + (size_t)tok0 * 16 + 15);
        float r1 = __ldg(ref + (size_t)(tok0 + 1) * 16 + 15);
        #pragma unroll
        for (int k = 0; k < 16; k++) { aX0[k] *= r0; aX1[k] *= r1; }
        jn_mat(jn0, aX0, aY0, std::make_integer_sequence<int, 16>{});
        jn_mat(jn1, aX1, aY1, std::make_integer_sequence<int, 16>{});
    }

    // ---- write feats over the consumed x tiles: float4 [kq=4][c=64] ----
    __syncwarp();
    {
        float4* f0 = reinterpret_cast<float4*>(tb + s0 * 1024);
        float4* f1 = reinterpret_cast<float4*>(tb + (s0 + 1) * 1024);
        #pragma unroll
        for (int kq = 0; kq < 4; kq++) {
            f0[kq * 64 + lane]      = make_float4(prod0[kq*4], prod0[kq*4+1], prod0[kq*4+2], prod0[kq*4+3]);
            f0[kq * 64 + 32 + lane] = make_float4(jn0[kq*4],   jn0[kq*4+1],   jn0[kq*4+2],   jn0[kq*4+3]);
            f1[kq * 64 + lane]      = make_float4(prod1[kq*4], prod1[kq*4+1], prod1[kq*4+2], prod1[kq*4+3]);
            f1[kq * 64 + 32 + lane] = make_float4(jn1[kq*4],   jn1[kq*4+1],   jn1[kq*4+2],   jn1[kq*4+3]);
        }
    }
    __syncthreads();   // all warps done with WPa/WPb

    // ---- swap in final weights ----
    {
        float4*       d = reinterpret_cast<float4*>(wbuf);
        const float4* s = reinterpret_cast<const float4*>(g_WF2);
        for (int i = tid; i < 5 * 64 * 32 * 2 / 4; i += THREADS) d[i] = s[i];
    }
    __syncthreads();

    // ---- Phase C: final projection, lane = o (and o+32), 2 tokens share ug ----
    float aO0[16] = {}, aP0[16] = {}, aO1[16] = {}, aP1[16] = {};
    {
        const float4* f0 = reinterpret_cast<const float4*>(tb + s0 * 1024);
        const float4* f1 = reinterpret_cast<const float4*>(tb + (s0 + 1) * 1024);
        const float2* WF = reinterpret_cast<const float2*>(wbuf);
        #pragma unroll 2
        for (int cc = 0; cc < 64; cc++) {
            float2 ug[5];
            #pragma unroll
            for (int g = 0; g < 5; g++) ug[g] = WF[(g * 64 + cc) * 32 + lane];
            {
                float4 a = f0[0*64+cc], b = f0[1*64+cc], c = f0[2*64+cc], d = f0[3*64+cc];
                float fk[16] = {a.x,a.y,a.z,a.w, b.x,b.y,b.z,b.w,
                                c.x,c.y,c.z,c.w, d.x,d.y,d.z,d.w};
                pair_fma(aO0, aP0, fk, ug, std::make_integer_sequence<int, 16>{});
            }
            {
                float4 a = f1[0*64+cc], b = f1[1*64+cc], c = f1[2*64+cc], d = f1[3*64+cc];
                float fk[16] = {a.x,a.y,a.z,a.w, b.x,b.y,b.z,b.w,
                                c.x,c.y,c.z,c.w, d.x,d.y,d.z,d.w};
                pair_fma(aO1, aP1, fk, ug, std::make_integer_sequence<int, 16>{});
            }
        }
    }

    // ---- store: out[tok][o][k], float4 over k ----
    {
        float4* o0 = reinterpret_cast<float4*>(out + (size_t)tok0 * 1024);
        float4* o1 = reinterpret_cast<float4*>(out + (size_t)(tok0 + 1) * 1024);
        #pragma unroll
        for (int kq = 0; kq < 4; kq++) {
            o0[lane * 4 + kq]        = make_float4(aO0[kq*4], aO0[kq*4+1], aO0[kq*4+2], aO0[kq*4+3]);
            o0[(lane + 32) * 4 + kq] = make_float4(aP0[kq*4], aP0[kq*4+1], aP0[kq*4+2], aP0[kq*4+3]);
            o1[lane * 4 + kq]        = make_float4(aO1[kq*4], aO1[kq*4+1], aO1[kq*4+2], aO1[kq*4+3]);
            o1[(lane + 32) * 4 + kq] = make_float4(aP1[kq*4], aP1[kq*4+1], aP1[kq*4+2], aP1[kq*4+3]);
        }
    }
}

// ---------------------------------------------------------------------------
// Launch
// ---------------------------------------------------------------------------
extern "C" void kernel_launch(void* const* d_in, const int* in_sizes, int n_in,
                              void* d_out, int out_size) {
    const float* x   = (const float*)d_in[0];
    const float* ref = (const float*)d_in[1];
    const float* wpx = (const float*)d_in[2];
    const float* wpy = (const float*)d_in[3];
    const float* wjx = (const float*)d_in[4];
    const float* wjy = (const float*)d_in[5];
    const float* wf  = (const float*)d_in[6];
    float* out = (float*)d_out;

    prep_kernel<<<40, 256>>>(wpx, wpy, wjx, wjy, wf);

    cudaFuncSetAttribute(gbl_kernel, cudaFuncAttributeMaxDynamicSharedMemorySize, SMEM_BYTES);
    gbl_kernel<<<NBLOCKS, THREADS, SMEM_BYTES>>>(x, ref, out);
}

// round 6
// speedup vs baseline: 1.4110x; 1.2535x over previous
#include <cuda_runtime.h>
#include <utility>
#include <cstddef>

using u64 = unsigned long long;

// ---------------------------------------------------------------------------
// packed f32x2 primitives (FFMA2 exists only via PTX fma.rn.f32x2)
// ---------------------------------------------------------------------------
__device__ __forceinline__ u64 pack2(float lo, float hi) {
    u64 r; asm("mov.b64 %0, {%1, %2};" : "=l"(r) : "f"(lo), "f"(hi)); return r;
}
__device__ __forceinline__ void unpack2(u64 v, float& lo, float& hi) {
    asm("mov.b64 {%0, %1}, %2;" : "=f"(lo), "=f"(hi) : "l"(v));
}
__device__ __forceinline__ void fma2(u64& d, u64 a, u64 b) {
    asm("fma.rn.f32x2 %0, %1, %2, %3;" : "=l"(d) : "l"(a), "l"(b), "l"(d));
}

// 8 packed FMAs covering 16 permuted blade positions.
// Position order: blades [1,2, 3,4, 5,6, 7,8, 9,10, 11,12, 13,14, 0,15]
// pair grades:     g1    g1   g2   g2   g2    g3     g3    (g0,g4)
// pack index:      p0    p0   p1   p1   p1    p2     p2      p3
#define DO8(acc, qa, qb, qc, qd, p0, p1, p2, p3)                         \
    do {                                                                 \
        fma2((acc)[0], (qa).x, (p0)); fma2((acc)[1], (qa).y, (p0));      \
        fma2((acc)[2], (qb).x, (p1)); fma2((acc)[3], (qb).y, (p1));      \
        fma2((acc)[4], (qc).x, (p1)); fma2((acc)[5], (qc).y, (p2));      \
        fma2((acc)[6], (qd).x, (p2)); fma2((acc)[7], (qd).y, (p3));      \
    } while (0)

// unpack 8 pairs (permuted positions) into blade-indexed scalars
#define UNPK(acc, arr)                                                   \
    do {                                                                 \
        unpack2((acc)[0], (arr)[1],  (arr)[2]);                          \
        unpack2((acc)[1], (arr)[3],  (arr)[4]);                          \
        unpack2((acc)[2], (arr)[5],  (arr)[6]);                          \
        unpack2((acc)[3], (arr)[7],  (arr)[8]);                          \
        unpack2((acc)[4], (arr)[9],  (arr)[10]);                         \
        unpack2((acc)[5], (arr)[11], (arr)[12]);                         \
        unpack2((acc)[6], (arr)[13], (arr)[14]);                         \
        unpack2((acc)[7], (arr)[0],  (arr)[15]);                         \
    } while (0)

// ---------------------------------------------------------------------------
// Compile-time Clifford algebra G(3,0,1) tables
// Blade order: 1,e0,e1,e2,e3,e01,e02,e03,e12,e13,e23,e012,e013,e023,e123,e0123
// ---------------------------------------------------------------------------
namespace ga {

constexpr int MASK[16]  = {0,1,2,4,8,3,5,9,6,10,12,7,11,13,14,15};

constexpr int mask_to_idx(int m) {
    int r = 0;
    for (int i = 0; i < 16; i++) if (MASK[i] == m) r = i;
    return r;
}
constexpr int swaps(int a, int b) {
    int s = 0;
    for (int q = 0; q < 4; q++)
        if ((b >> q) & 1)
            for (int p = q + 1; p < 4; p++)
                if ((a >> p) & 1) s++;
    return s;
}
constexpr float rsign(int a, int b) { return (swaps(a, b) & 1) ? -1.0f : 1.0f; }

struct Tab { float s[16][16]; int k[16][16]; };

constexpr Tab make_gp() {
    Tab t{};
    for (int i = 0; i < 16; i++)
        for (int j = 0; j < 16; j++) {
            int a = MASK[i], b = MASK[j];
            float sg = rsign(a, b);
            if (a & b & 1) sg = 0.0f;            // e0^2 = 0
            t.s[i][j] = sg;
            t.k[i][j] = mask_to_idx(a ^ b);
        }
    return t;
}
constexpr float dsign(int i) { return rsign(MASK[i], 15 ^ MASK[i]); }
constexpr Tab make_join() {
    Tab t{};
    for (int i = 0; i < 16; i++)
        for (int j = 0; j < 16; j++) {
            int ci = 15 ^ MASK[i], cj = 15 ^ MASK[j];
            if (ci & cj) { t.s[i][j] = 0.0f; t.k[i][j] = 0; }
            else {
                int m = ci | cj;
                int p = mask_to_idx(15 ^ m);
                t.s[i][j] = dsign(i) * dsign(j) * rsign(ci, cj) * dsign(p);
                t.k[i][j] = p;
            }
        }
    return t;
}
constexpr Tab GP = make_gp();
constexpr Tab JN = make_join();

} // namespace ga

// static-for sparse bilinears (all indices compile-time)
template<int I, int J>
__device__ __forceinline__ void gp_term(float* p, const float* a, const float* b) {
    constexpr float s = ga::GP.s[I][J];
    constexpr int   k = ga::GP.k[I][J];
    if constexpr (s != 0.0f) p[k] += s * a[I] * b[J];
}
template<int I, int... Js>
__device__ __forceinline__ void gp_row(float* p, const float* a, const float* b,
                                       std::integer_sequence<int, Js...>) {
    (gp_term<I, Js>(p, a, b), ...);
}
template<int... Is>
__device__ __forceinline__ void gp_mat(float* p, const float* a, const float* b,
                                       std::integer_sequence<int, Is...>) {
    (gp_row<Is>(p, a, b, std::make_integer_sequence<int, 16>{}), ...);
}
template<int I, int J>
__device__ __forceinline__ void jn_term(float* p, const float* a, const float* b) {
    constexpr float s = ga::JN.s[I][J];
    constexpr int   k = ga::JN.k[I][J];
    if constexpr (s != 0.0f) p[k] += s * a[I] * b[J];
}
template<int I, int... Js>
__device__ __forceinline__ void jn_row(float* p, const float* a, const float* b,
                                       std::integer_sequence<int, Js...>) {
    (jn_term<I, Js>(p, a, b), ...);
}
template<int... Is>
__device__ __forceinline__ void jn_mat(float* p, const float* a, const float* b,
                                       std::integer_sequence<int, Is...>) {
    (jn_row<Is>(p, a, b, std::make_integer_sequence<int, 16>{}), ...);
}

// ---------------------------------------------------------------------------
// Problem constants: B=32, N=1024, Cin=64, Cout=64, H=32 -> 32768 tokens
// ---------------------------------------------------------------------------
static constexpr int TOKENS   = 32 * 1024;
static constexpr int WARPS_PB = 8;
static constexpr int TPW      = 2;
static constexpr int TOK_PB   = WARPS_PB * TPW;     // 16
static constexpr int NGROUPS  = TOKENS / TOK_PB;    // 2048
static constexpr int THREADS  = WARPS_PB * 32;
static constexpr int GRID     = 152;                // persistent, 1 CTA/SM

// weight scratch in gmem (no allocations)
// WP4: [5 g][64 i][32 c] float4 {prodX, prodY, joinX, joinY}
// WF2: [5 g][64 cc][32 o] float2 {col o, col o+32}
__device__ float g_WP4[5 * 64 * 32 * 4];
__device__ float g_WF2[5 * 64 * 32 * 2];

__global__ void prep_kernel(const float* __restrict__ wpx, const float* __restrict__ wpy,
                            const float* __restrict__ wjx, const float* __restrict__ wjy,
                            const float* __restrict__ wf) {
    int idx = blockIdx.x * blockDim.x + threadIdx.x;     // over 10240
    if (idx < 5 * 64 * 32) {
        int c = idx & 31;
        int i = (idx >> 5) & 63;
        int g = idx >> 11;
        int src = (g * 32 + c) * 64 + i;                 // proj weights [5][32][64]
        g_WP4[idx * 4 + 0] = wpx[src];
        g_WP4[idx * 4 + 1] = wpy[src];
        g_WP4[idx * 4 + 2] = wjx[src];
        g_WP4[idx * 4 + 3] = wjy[src];
        g_WF2[idx * 2 + 0] = wf[(g * 64 + c)      * 64 + i];   // [5][64 o][64 cc]
        g_WF2[idx * 2 + 1] = wf[(g * 64 + c + 32) * 64 + i];
    }
}

// smem: tb 16 slots x 1024 floats (x permuted -> feats swizzled) = 64KB
//       wbuf 40960 floats = WP4 160KB; WF (20480 floats) overlays its tail
static constexpr int TB_FLOATS  = TOK_PB * 1024;            // 16384
static constexpr int WP4_FLOATS = 5 * 64 * 32 * 4;          // 40960
static constexpr int WF_FLOATS  = 5 * 64 * 32 * 2;          // 20480
static constexpr int WF_OFF     = WP4_FLOATS - WF_FLOATS;   // 20480
static constexpr int SMEM_BYTES = (TB_FLOATS + WP4_FLOATS) * 4;  // 229376

__global__ __launch_bounds__(THREADS, 1)
void gbl_kernel(const float* __restrict__ x, const float* __restrict__ ref,
                float* __restrict__ out) {
    extern __shared__ float smem[];
    float* tb   = smem;
    float* wbuf = smem + TB_FLOATS;

    const int tid  = threadIdx.x;
    const int w    = tid >> 5;
    const int lane = tid & 31;
    const int q    = lane & 3;          // staging sub-index
    const int s0   = w * 2;

    // ---- stage full WP4 once per block ----
    {
        float4*       d = reinterpret_cast<float4*>(wbuf);
        const float4* s = reinterpret_cast<const float4*>(g_WP4);
        for (int i = tid; i < WP4_FLOATS / 4; i += THREADS) d[i] = s[i];
    }

    bool first = true;
    for (int grp = blockIdx.x; grp < NGROUPS; grp += gridDim.x, first = false) {
        const int tok0 = grp * TOK_PB + s0;

        if (!first) {
            __syncthreads();   // previous group fully done (WF reads, tb reads)
            // restage WP4 tail that WF clobbered
            float4*       d = reinterpret_cast<float4*>(wbuf + WF_OFF);
            const float4* s = reinterpret_cast<const float4*>(g_WP4 + WF_OFF);
            for (int i = tid; i < WF_FLOATS / 4; i += THREADS) d[i] = s[i];
        }

        // ---- stage this warp's 2 tokens, blade-permuted, into tb ----
        // permuted positions hold blades [1..14, 0, 15]
        {
            #pragma unroll
            for (int t = 0; t < 2; t++) {
                const float4* xg = reinterpret_cast<const float4*>(x + (size_t)(tok0 + t) * 1024);
                float4* dst = reinterpret_cast<float4*>(tb + (s0 + t) * 1024);
                #pragma unroll
                for (int rep = 0; rep < 8; rep++) {
                    float4 v = xg[rep * 32 + lane];          // i = rep*8 + lane>>2, quad q
                    float firstx = __shfl_sync(0xffffffffu, v.x, lane & ~3);
                    float nextx  = __shfl_down_sync(0xffffffffu, v.x, 1);
                    float4 o;
                    if (q < 3) o = make_float4(v.y, v.z, v.w, nextx);
                    else       o = make_float4(v.y, v.z, firstx, v.w);
                    dst[rep * 32 + (lane >> 2) * 4 + q] = o;   // channel i quad q (FIXED)
                }
            }
        }
        __syncthreads();    // WP4 tail + x ready

        // ================= Phase A: fused 4-tensor projection =================
        u64 aPX0[8] = {}, aPY0[8] = {}, aJX0[8] = {}, aJY0[8] = {};
        u64 aPX1[8] = {}, aPY1[8] = {}, aJX1[8] = {}, aJY1[8] = {};
        {
            const float4* W4 = reinterpret_cast<const float4*>(wbuf);
            const ulonglong2* xv0 = reinterpret_cast<const ulonglong2*>(tb + s0 * 1024);
            const ulonglong2* xv1 = reinterpret_cast<const ulonglong2*>(tb + (s0 + 1) * 1024);
            #pragma unroll 1
            for (int i = 0; i < 64; i++) {
                float4 wq[5];
                #pragma unroll
                for (int g = 0; g < 5; g++) wq[g] = W4[(g * 64 + i) * 32 + lane];
                ulonglong2 a0 = xv0[i * 4 + 0], b0 = xv0[i * 4 + 1],
                           c0 = xv0[i * 4 + 2], d0 = xv0[i * 4 + 3];
                ulonglong2 a1 = xv1[i * 4 + 0], b1 = xv1[i * 4 + 1],
                           c1 = xv1[i * 4 + 2], d1 = xv1[i * 4 + 3];
                {   // prodX (.x)
                    u64 p0 = pack2(wq[1].x, wq[1].x), p1 = pack2(wq[2].x, wq[2].x);
                    u64 p2 = pack2(wq[3].x, wq[3].x), p3 = pack2(wq[0].x, wq[4].x);
                    DO8(aPX0, a0, b0, c0, d0, p0, p1, p2, p3);
                    DO8(aPX1, a1, b1, c1, d1, p0, p1, p2, p3);
                }
                {   // prodY (.y)
                    u64 p0 = pack2(wq[1].y, wq[1].y), p1 = pack2(wq[2].y, wq[2].y);
                    u64 p2 = pack2(wq[3].y, wq[3].y), p3 = pack2(wq[0].y, wq[4].y);
                    DO8(aPY0, a0, b0, c0, d0, p0, p1, p2, p3);
                    DO8(aPY1, a1, b1, c1, d1, p0, p1, p2, p3);
                }
                {   // joinX (.z)
                    u64 p0 = pack2(wq[1].z, wq[1].z), p1 = pack2(wq[2].z, wq[2].z);
                    u64 p2 = pack2(wq[3].z, wq[3].z), p3 = pack2(wq[0].z, wq[4].z);
                    DO8(aJX0, a0, b0, c0, d0, p0, p1, p2, p3);
                    DO8(aJX1, a1, b1, c1, d1, p0, p1, p2, p3);
                }
                {   // joinY (.w)
                    u64 p0 = pack2(wq[1].w, wq[1].w), p1 = pack2(wq[2].w, wq[2].w);
                    u64 p2 = pack2(wq[3].w, wq[3].w), p3 = pack2(wq[0].w, wq[4].w);
                    DO8(aJY0, a0, b0, c0, d0, p0, p1, p2, p3);
                    DO8(aJY1, a1, b1, c1, d1, p0, p1, p2, p3);
                }
            }
        }

        // ================= Phase B: sparse bilinears, feats store =============
        float r0 = __ldg(ref + (size_t)tok0 * 16 + 15);
        float r1 = __ldg(ref + (size_t)(tok0 + 1) * 16 + 15);
        #pragma unroll
        for (int t = 0; t < 2; t++) {
            float px[16], py[16], jx[16], jy[16];
            if (t == 0) { UNPK(aPX0, px); UNPK(aPY0, py); UNPK(aJX0, jx); UNPK(aJY0, jy); }
            else        { UNPK(aPX1, px); UNPK(aPY1, py); UNPK(aJX1, jx); UNPK(aJY1, jy); }
            float r15 = (t == 0) ? r0 : r1;
            #pragma unroll
            for (int k = 0; k < 16; k++) jx[k] *= r15;

            float prod[16] = {}, jn[16] = {};
            gp_mat(prod, px, py, std::make_integer_sequence<int, 16>{});
            jn_mat(jn,   jx, jy, std::make_integer_sequence<int, 16>{});

            // feats overlay x slot, permuted positions + XOR-swizzled float4 slots
            float4* fb = reinterpret_cast<float4*>(tb + (s0 + t) * 1024);
            int ccP = lane, ccJ = lane + 32;
            int swP = ccP & 3, swJ = ccJ & 3;
            fb[ccP * 4 + (0 ^ swP)] = make_float4(prod[1],  prod[2],  prod[3],  prod[4]);
            fb[ccP * 4 + (1 ^ swP)] = make_float4(prod[5],  prod[6],  prod[7],  prod[8]);
            fb[ccP * 4 + (2 ^ swP)] = make_float4(prod[9],  prod[10], prod[11], prod[12]);
            fb[ccP * 4 + (3 ^ swP)] = make_float4(prod[13], prod[14], prod[0],  prod[15]);
            fb[ccJ * 4 + (0 ^ swJ)] = make_float4(jn[1],  jn[2],  jn[3],  jn[4]);
            fb[ccJ * 4 + (1 ^ swJ)] = make_float4(jn[5],  jn[6],  jn[7],  jn[8]);
            fb[ccJ * 4 + (2 ^ swJ)] = make_float4(jn[9],  jn[10], jn[11], jn[12]);
            fb[ccJ * 4 + (3 ^ swJ)] = make_float4(jn[13], jn[14], jn[0],  jn[15]);
        }
        __syncthreads();   // everyone done reading WP4 tail

        // ---- overlay WF onto wbuf tail ----
        {
            float4*       d = reinterpret_cast<float4*>(wbuf + WF_OFF);
            const float4* s = reinterpret_cast<const float4*>(g_WF2);
            for (int i = tid; i < WF_FLOATS / 4; i += THREADS) d[i] = s[i];
        }
        __syncthreads();

        // ================= Phase C: final projection ==========================
        u64 o0a[8] = {}, o0b[8] = {}, o1a[8] = {}, o1b[8] = {};
        {
            const float2* WF = reinterpret_cast<const float2*>(wbuf + WF_OFF);
            const ulonglong2* fb0 = reinterpret_cast<const ulonglong2*>(tb + s0 * 1024);
            const ulonglong2* fb1 = reinterpret_cast<const ulonglong2*>(tb + (s0 + 1) * 1024);
            #pragma unroll 1
            for (int cc = 0; cc < 64; cc++) {
                float2 w2[5];
                #pragma unroll
                for (int g = 0; g < 5; g++) w2[g] = WF[(g * 64 + cc) * 32 + lane];
                int sw = cc & 3;
                ulonglong2 f00 = fb0[cc * 4 + (0 ^ sw)], f01 = fb0[cc * 4 + (1 ^ sw)],
                           f02 = fb0[cc * 4 + (2 ^ sw)], f03 = fb0[cc * 4 + (3 ^ sw)];
                ulonglong2 f10 = fb1[cc * 4 + (0 ^ sw)], f11 = fb1[cc * 4 + (1 ^ sw)],
                           f12 = fb1[cc * 4 + (2 ^ sw)], f13 = fb1[cc * 4 + (3 ^ sw)];
                u64 pa0 = pack2(w2[1].x, w2[1].x), pa1 = pack2(w2[2].x, w2[2].x);
                u64 pa2 = pack2(w2[3].x, w2[3].x), pa3 = pack2(w2[0].x, w2[4].x);
                u64 pb0 = pack2(w2[1].y, w2[1].y), pb1 = pack2(w2[2].y, w2[2].y);
                u64 pb2 = pack2(w2[3].y, w2[3].y), pb3 = pack2(w2[0].y, w2[4].y);
                DO8(o0a, f00, f01, f02, f03, pa0, pa1, pa2, pa3);
                DO8(o0b, f00, f01, f02, f03, pb0, pb1, pb2, pb3);
                DO8(o1a, f10, f11, f12, f13, pa0, pa1, pa2, pa3);
                DO8(o1b, f10, f11, f12, f13, pb0, pb1, pb2, pb3);
            }
        }

        // ---- stores: natural blade order ----
        {
            float4* op0 = reinterpret_cast<float4*>(out + (size_t)tok0 * 1024);
            float4* op1 = reinterpret_cast<float4*>(out + (size_t)(tok0 + 1) * 1024);
            float v[16];
            UNPK(o0a, v);
            op0[lane * 4 + 0] = make_float4(v[0], v[1], v[2], v[3]);
            op0[lane * 4 + 1] = make_float4(v[4], v[5], v[6], v[7]);
            op0[lane * 4 + 2] = make_float4(v[8], v[9], v[10], v[11]);
            op0[lane * 4 + 3] = make_float4(v[12], v[13], v[14], v[15]);
            UNPK(o0b, v);
            op0[(lane + 32) * 4 + 0] = make_float4(v[0], v[1], v[2], v[3]);
            op0[(lane + 32) * 4 + 1] = make_float4(v[4], v[5], v[6], v[7]);
            op0[(lane + 32) * 4 + 2] = make_float4(v[8], v[9], v[10], v[11]);
            op0[(lane + 32) * 4 + 3] = make_float4(v[12], v[13], v[14], v[15]);
            UNPK(o1a, v);
            op1[lane * 4 + 0] = make_float4(v[0], v[1], v[2], v[3]);
            op1[lane * 4 + 1] = make_float4(v[4], v[5], v[6], v[7]);
            op1[lane * 4 + 2] = make_float4(v[8], v[9], v[10], v[11]);
            op1[lane * 4 + 3] = make_float4(v[12], v[13], v[14], v[15]);
            UNPK(o1b, v);
            op1[(lane + 32) * 4 + 0] = make_float4(v[0], v[1], v[2], v[3]);
            op1[(lane + 32) * 4 + 1] = make_float4(v[4], v[5], v[6], v[7]);
            op1[(lane + 32) * 4 + 2] = make_float4(v[8], v[9], v[10], v[11]);
            op1[(lane + 32) * 4 + 3] = make_float4(v[12], v[13], v[14], v[15]);
        }
    }
}

// ---------------------------------------------------------------------------
extern "C" void kernel_launch(void* const* d_in, const int* in_sizes, int n_in,
                              void* d_out, int out_size) {
    const float* x   = (const float*)d_in[0];
    const float* ref = (const float*)d_in[1];
    const float* wpx = (const float*)d_in[2];
    const float* wpy = (const float*)d_in[3];
    const float* wjx = (const float*)d_in[4];
    const float* wjy = (const float*)d_in[5];
    const float* wf  = (const float*)d_in[6];
    float* out = (float*)d_out;

    prep_kernel<<<40, 256>>>(wpx, wpy, wjx, wjy, wf);

    cudaFuncSetAttribute(gbl_kernel, cudaFuncAttributeMaxDynamicSharedMemorySize, SMEM_BYTES);
    gbl_kernel<<<GRID, THREADS, SMEM_BYTES>>>(x, ref, out);
}

// round 7
// speedup vs baseline: 1.5524x; 1.1003x over previous
#include <cuda_runtime.h>
#include <cuda_fp16.h>
#include <utility>
#include <cstddef>

using u64 = unsigned long long;

// ---------------------------------------------------------------------------
// packed f32x2 primitives (FFMA2 exists only via PTX fma.rn.f32x2)
// ---------------------------------------------------------------------------
__device__ __forceinline__ u64 pack2(float lo, float hi) {
    u64 r; asm("mov.b64 %0, {%1, %2};" : "=l"(r) : "f"(lo), "f"(hi)); return r;
}
__device__ __forceinline__ void unpack2(u64 v, float& lo, float& hi) {
    asm("mov.b64 {%0, %1}, %2;" : "=f"(lo), "=f"(hi) : "l"(v));
}
__device__ __forceinline__ void fma2(u64& d, u64 a, u64 b) {
    asm("fma.rn.f32x2 %0, %1, %2, %3;" : "=l"(d) : "l"(a), "l"(b), "l"(d));
}
__device__ __forceinline__ float hlo(unsigned v) {
    __half2 h = *reinterpret_cast<__half2*>(&v); return __low2float(h);
}
__device__ __forceinline__ float hhi(unsigned v) {
    __half2 h = *reinterpret_cast<__half2*>(&v); return __high2float(h);
}

// 8 packed FMAs covering 16 permuted blade positions.
// Position order: blades [1,2, 3,4, 5,6, 7,8, 9,10, 11,12, 13,14, 0,15]
// pair grades:     g1    g1   g2   g2   g2    g3     g3    (g0,g4)
// pack index:      p0    p0   p1   p1   p1    p2     p2      p3
#define DO8(acc, qa, qb, qc, qd, p0, p1, p2, p3)                         \
    do {                                                                 \
        fma2((acc)[0], (qa).x, (p0)); fma2((acc)[1], (qa).y, (p0));      \
        fma2((acc)[2], (qb).x, (p1)); fma2((acc)[3], (qb).y, (p1));      \
        fma2((acc)[4], (qc).x, (p1)); fma2((acc)[5], (qc).y, (p2));      \
        fma2((acc)[6], (qd).x, (p2)); fma2((acc)[7], (qd).y, (p3));      \
    } while (0)

// unpack 8 pairs (permuted positions) into blade-indexed scalars
#define UNPK(acc, arr)                                                   \
    do {                                                                 \
        unpack2((acc)[0], (arr)[1],  (arr)[2]);                          \
        unpack2((acc)[1], (arr)[3],  (arr)[4]);                          \
        unpack2((acc)[2], (arr)[5],  (arr)[6]);                          \
        unpack2((acc)[3], (arr)[7],  (arr)[8]);                          \
        unpack2((acc)[4], (arr)[9],  (arr)[10]);                         \
        unpack2((acc)[5], (arr)[11], (arr)[12]);                         \
        unpack2((acc)[6], (arr)[13], (arr)[14]);                         \
        unpack2((acc)[7], (arr)[0],  (arr)[15]);                         \
    } while (0)

// ---------------------------------------------------------------------------
// Compile-time Clifford algebra G(3,0,1) tables
// Blade order: 1,e0,e1,e2,e3,e01,e02,e03,e12,e13,e23,e012,e013,e023,e123,e0123
// ---------------------------------------------------------------------------
namespace ga {

constexpr int MASK[16]  = {0,1,2,4,8,3,5,9,6,10,12,7,11,13,14,15};

constexpr int mask_to_idx(int m) {
    int r = 0;
    for (int i = 0; i < 16; i++) if (MASK[i] == m) r = i;
    return r;
}
constexpr int swaps(int a, int b) {
    int s = 0;
    for (int q = 0; q < 4; q++)
        if ((b >> q) & 1)
            for (int p = q + 1; p < 4; p++)
                if ((a >> p) & 1) s++;
    return s;
}
constexpr float rsign(int a, int b) { return (swaps(a, b) & 1) ? -1.0f : 1.0f; }

struct Tab { float s[16][16]; int k[16][16]; };

constexpr Tab make_gp() {
    Tab t{};
    for (int i = 0; i < 16; i++)
        for (int j = 0; j < 16; j++) {
            int a = MASK[i], b = MASK[j];
            float sg = rsign(a, b);
            if (a & b & 1) sg = 0.0f;            // e0^2 = 0
            t.s[i][j] = sg;
            t.k[i][j] = mask_to_idx(a ^ b);
        }
    return t;
}
constexpr float dsign(int i) { return rsign(MASK[i], 15 ^ MASK[i]); }
constexpr Tab make_join() {
    Tab t{};
    for (int i = 0; i < 16; i++)
        for (int j = 0; j < 16; j++) {
            int ci = 15 ^ MASK[i], cj = 15 ^ MASK[j];
            if (ci & cj) { t.s[i][j] = 0.0f; t.k[i][j] = 0; }
            else {
                int m = ci | cj;
                int p = mask_to_idx(15 ^ m);
                t.s[i][j] = dsign(i) * dsign(j) * rsign(ci, cj) * dsign(p);
                t.k[i][j] = p;
            }
        }
    return t;
}
constexpr Tab GP = make_gp();
constexpr Tab JN = make_join();

} // namespace ga

// static-for sparse bilinears (all indices compile-time)
template<int I, int J>
__device__ __forceinline__ void gp_term(float* p, const float* a, const float* b) {
    constexpr float s = ga::GP.s[I][J];
    constexpr int   k = ga::GP.k[I][J];
    if constexpr (s != 0.0f) p[k] += s * a[I] * b[J];
}
template<int I, int... Js>
__device__ __forceinline__ void gp_row(float* p, const float* a, const float* b,
                                       std::integer_sequence<int, Js...>) {
    (gp_term<I, Js>(p, a, b), ...);
}
template<int... Is>
__device__ __forceinline__ void gp_mat(float* p, const float* a, const float* b,
                                       std::integer_sequence<int, Is...>) {
    (gp_row<Is>(p, a, b, std::make_integer_sequence<int, 16>{}), ...);
}
template<int I, int J>
__device__ __forceinline__ void jn_term(float* p, const float* a, const float* b) {
    constexpr float s = ga::JN.s[I][J];
    constexpr int   k = ga::JN.k[I][J];
    if constexpr (s != 0.0f) p[k] += s * a[I] * b[J];
}
template<int I, int... Js>
__device__ __forceinline__ void jn_row(float* p, const float* a, const float* b,
                                       std::integer_sequence<int, Js...>) {
    (jn_term<I, Js>(p, a, b), ...);
}
template<int... Is>
__device__ __forceinline__ void jn_mat(float* p, const float* a, const float* b,
                                       std::integer_sequence<int, Is...>) {
    (jn_row<Is>(p, a, b, std::make_integer_sequence<int, 16>{}), ...);
}

// ---------------------------------------------------------------------------
// Problem constants: B=32, N=1024, Cin=64, Cout=64, H=32 -> 32768 tokens
// ---------------------------------------------------------------------------
static constexpr int TOKENS   = 32 * 1024;
static constexpr int NPAIRS   = TOKENS / 2;         // 16384 token pairs
static constexpr int WARPS_PB = 8;
static constexpr int THREADS  = WARPS_PB * 32;
static constexpr int GRID     = 152;                // persistent, 1 CTA/SM

// fp16 weight tables (static __device__ -> no allocation)
// g_WPH: per (i, c) slot: 10 half2  [g0:(PX,PY) (JX,JY), g1:..., g2, g3, g4]
// g_WFH: per (cc, o) slot: 6 half2  [g0:(o,o+32), g1, g2, g3, g4, pad]
__device__ __align__(16) __half2 g_WPH[64 * 32 * 10];
__device__ __align__(16) __half2 g_WFH[64 * 32 * 6];

__global__ void prep_kernel(const float* __restrict__ wpx, const float* __restrict__ wpy,
                            const float* __restrict__ wjx, const float* __restrict__ wjy,
                            const float* __restrict__ wf) {
    int idx = blockIdx.x * blockDim.x + threadIdx.x;     // over 2048 (i,c) slots
    if (idx < 64 * 32) {
        int c = idx & 31;            // lane channel (c for proj, o for final)
        int i = idx >> 5;            // reduction index (i for proj, cc for final)
        #pragma unroll
        for (int g = 0; g < 5; g++) {
            int src = (g * 32 + c) * 64 + i;             // proj weights [5][32][64]
            g_WPH[idx * 10 + g * 2 + 0] = __floats2half2_rn(wpx[src], wpy[src]);
            g_WPH[idx * 10 + g * 2 + 1] = __floats2half2_rn(wjx[src], wjy[src]);
            // final weights [5][64 o][64 cc]; here c = o, i = cc
            g_WFH[idx * 6 + g] = __floats2half2_rn(wf[(g * 64 + c) * 64 + i],
                                                   wf[(g * 64 + c + 32) * 64 + i]);
        }
        g_WFH[idx * 6 + 5] = __floats2half2_rn(0.f, 0.f);
    }
}

// smem: tb 16 slots x 1024 floats (x permuted / feats swizzled)  = 64 KB
//       WPH 20480 half2 = 80 KB,  WFH 12288 half2 = 48 KB   -> 192 KB total
static constexpr int TB_FLOATS  = 16 * 1024;
static constexpr int WPH_H2     = 64 * 32 * 10;      // 20480
static constexpr int WFH_H2     = 64 * 32 * 6;       // 12288
static constexpr int SMEM_BYTES = TB_FLOATS * 4 + WPH_H2 * 4 + WFH_H2 * 4;  // 196608

// build the 4 u64 packs for one tensor from 5 converted floats
#define MK_PACKS(p0, p1, p2, p3, f0, f1, f2, f3, f4)                      \
    u64 p0 = pack2(f1, f1), p1 = pack2(f2, f2),                           \
        p2 = pack2(f3, f3), p3 = pack2(f0, f4)

__global__ __launch_bounds__(THREADS, 1)
void gbl_kernel(const float* __restrict__ x, const float* __restrict__ ref,
                float* __restrict__ out) {
    extern __shared__ float smem[];
    float*   tb  = smem;
    __half2* WPH = reinterpret_cast<__half2*>(smem + TB_FLOATS);
    __half2* WFH = WPH + WPH_H2;

    const int tid  = threadIdx.x;
    const int w    = tid >> 5;
    const int lane = tid & 31;
    const int q    = lane & 3;
    const int s0   = w * 2;

    // ---- stage both weight tables once (then no block barriers ever) ----
    {
        uint4*       d = reinterpret_cast<uint4*>(WPH);
        const uint4* s = reinterpret_cast<const uint4*>(g_WPH);
        for (int i = tid; i < WPH_H2 / 4; i += THREADS) d[i] = s[i];
        uint4*       d2 = reinterpret_cast<uint4*>(WFH);
        const uint4* s2 = reinterpret_cast<const uint4*>(g_WFH);
        for (int i = tid; i < WFH_H2 / 4; i += THREADS) d2[i] = s2[i];
    }
    __syncthreads();

    // ---- barrier-free persistent loop: each warp owns its token pair ----
    for (int pair = blockIdx.x * WARPS_PB + w; pair < NPAIRS; pair += GRID * WARPS_PB) {
        const int tok0 = pair * 2;

        // stage 2 tokens, blade-permuted [1..14,0,15], into warp-private slots
        #pragma unroll
        for (int t = 0; t < 2; t++) {
            const float4* xg = reinterpret_cast<const float4*>(x + (size_t)(tok0 + t) * 1024);
            float4* dst = reinterpret_cast<float4*>(tb + (s0 + t) * 1024);
            #pragma unroll
            for (int rep = 0; rep < 8; rep++) {
                float4 v = xg[rep * 32 + lane];          // channel i = rep*8 + lane>>2, quad q
                float firstx = __shfl_sync(0xffffffffu, v.x, lane & ~3);
                float nextx  = __shfl_down_sync(0xffffffffu, v.x, 1);
                float4 o;
                if (q < 3) o = make_float4(v.y, v.z, v.w, nextx);
                else       o = make_float4(v.y, v.z, firstx, v.w);
                dst[rep * 32 + (lane >> 2) * 4 + q] = o;
            }
        }
        __syncwarp();

        // ================= Phase A: fused 4-tensor projection =================
        u64 aPX0[8] = {}, aPY0[8] = {}, aJX0[8] = {}, aJY0[8] = {};
        u64 aPX1[8] = {}, aPY1[8] = {}, aJX1[8] = {}, aJY1[8] = {};
        {
            const uint2* Wu = reinterpret_cast<const uint2*>(WPH) + lane * 5;
            const ulonglong2* xv0 = reinterpret_cast<const ulonglong2*>(tb + s0 * 1024);
            const ulonglong2* xv1 = reinterpret_cast<const ulonglong2*>(tb + (s0 + 1) * 1024);
            #pragma unroll 1
            for (int i = 0; i < 64; i++, Wu += 32 * 5) {
                uint2 ua = Wu[0], ub = Wu[1], uc = Wu[2], ud = Wu[3], ue = Wu[4];
                ulonglong2 a0 = xv0[i * 4 + 0], b0 = xv0[i * 4 + 1],
                           c0 = xv0[i * 4 + 2], d0 = xv0[i * 4 + 3];
                ulonglong2 a1 = xv1[i * 4 + 0], b1 = xv1[i * 4 + 1],
                           c1 = xv1[i * 4 + 2], d1 = xv1[i * 4 + 3];
                {   // prodX = low halves of pair-0 (.x) words
                    MK_PACKS(p0, p1, p2, p3, hlo(ua.x), hlo(ub.x), hlo(uc.x), hlo(ud.x), hlo(ue.x));
                    DO8(aPX0, a0, b0, c0, d0, p0, p1, p2, p3);
                    DO8(aPX1, a1, b1, c1, d1, p0, p1, p2, p3);
                }
                {   // prodY = high halves of pair-0
                    MK_PACKS(p0, p1, p2, p3, hhi(ua.x), hhi(ub.x), hhi(uc.x), hhi(ud.x), hhi(ue.x));
                    DO8(aPY0, a0, b0, c0, d0, p0, p1, p2, p3);
                    DO8(aPY1, a1, b1, c1, d1, p0, p1, p2, p3);
                }
                {   // joinX = low halves of pair-1 (.y) words
                    MK_PACKS(p0, p1, p2, p3, hlo(ua.y), hlo(ub.y), hlo(uc.y), hlo(ud.y), hlo(ue.y));
                    DO8(aJX0, a0, b0, c0, d0, p0, p1, p2, p3);
                    DO8(aJX1, a1, b1, c1, d1, p0, p1, p2, p3);
                }
                {   // joinY = high halves of pair-1
                    MK_PACKS(p0, p1, p2, p3, hhi(ua.y), hhi(ub.y), hhi(uc.y), hhi(ud.y), hhi(ue.y));
                    DO8(aJY0, a0, b0, c0, d0, p0, p1, p2, p3);
                    DO8(aJY1, a1, b1, c1, d1, p0, p1, p2, p3);
                }
            }
        }

        // ================= Phase B: sparse bilinears, feats store =============
        float r0 = __ldg(ref + (size_t)tok0 * 16 + 15);
        float r1 = __ldg(ref + (size_t)(tok0 + 1) * 16 + 15);
        #pragma unroll
        for (int t = 0; t < 2; t++) {
            float px[16], py[16], jx[16], jy[16];
            if (t == 0) { UNPK(aPX0, px); UNPK(aPY0, py); UNPK(aJX0, jx); UNPK(aJY0, jy); }
            else        { UNPK(aPX1, px); UNPK(aPY1, py); UNPK(aJX1, jx); UNPK(aJY1, jy); }
            float r15 = (t == 0) ? r0 : r1;
            #pragma unroll
            for (int k = 0; k < 16; k++) jx[k] *= r15;

            float prod[16] = {}, jn[16] = {};
            gp_mat(prod, px, py, std::make_integer_sequence<int, 16>{});
            jn_mat(jn,   jx, jy, std::make_integer_sequence<int, 16>{});

            // feats overlay x slot, permuted positions + XOR-swizzled float4 slots
            float4* fb = reinterpret_cast<float4*>(tb + (s0 + t) * 1024);
            int ccP = lane, ccJ = lane + 32;
            int swP = ccP & 3, swJ = ccJ & 3;
            fb[ccP * 4 + (0 ^ swP)] = make_float4(prod[1],  prod[2],  prod[3],  prod[4]);
            fb[ccP * 4 + (1 ^ swP)] = make_float4(prod[5],  prod[6],  prod[7],  prod[8]);
            fb[ccP * 4 + (2 ^ swP)] = make_float4(prod[9],  prod[10], prod[11], prod[12]);
            fb[ccP * 4 + (3 ^ swP)] = make_float4(prod[13], prod[14], prod[0],  prod[15]);
            fb[ccJ * 4 + (0 ^ swJ)] = make_float4(jn[1],  jn[2],  jn[3],  jn[4]);
            fb[ccJ * 4 + (1 ^ swJ)] = make_float4(jn[5],  jn[6],  jn[7],  jn[8]);
            fb[ccJ * 4 + (2 ^ swJ)] = make_float4(jn[9],  jn[10], jn[11], jn[12]);
            fb[ccJ * 4 + (3 ^ swJ)] = make_float4(jn[13], jn[14], jn[0],  jn[15]);
        }
        __syncwarp();

        // ================= Phase C: final projection ==========================
        u64 o0a[8] = {}, o0b[8] = {}, o1a[8] = {}, o1b[8] = {};
        {
            const uint2* Vu = reinterpret_cast<const uint2*>(WFH) + lane * 3;
            const ulonglong2* fb0 = reinterpret_cast<const ulonglong2*>(tb + s0 * 1024);
            const ulonglong2* fb1 = reinterpret_cast<const ulonglong2*>(tb + (s0 + 1) * 1024);
            #pragma unroll 1
            for (int cc = 0; cc < 64; cc++, Vu += 32 * 3) {
                uint2 va = Vu[0], vb = Vu[1], vc = Vu[2];   // (g0,g1) (g2,g3) (g4,pad)
                int sw = cc & 3;
                ulonglong2 f00 = fb0[cc * 4 + (0 ^ sw)], f01 = fb0[cc * 4 + (1 ^ sw)],
                           f02 = fb0[cc * 4 + (2 ^ sw)], f03 = fb0[cc * 4 + (3 ^ sw)];
                ulonglong2 f10 = fb1[cc * 4 + (0 ^ sw)], f11 = fb1[cc * 4 + (1 ^ sw)],
                           f12 = fb1[cc * 4 + (2 ^ sw)], f13 = fb1[cc * 4 + (3 ^ sw)];
                {   // output o = lane (low halves)
                    MK_PACKS(p0, p1, p2, p3, hlo(va.x), hlo(va.y), hlo(vb.x), hlo(vb.y), hlo(vc.x));
                    DO8(o0a, f00, f01, f02, f03, p0, p1, p2, p3);
                    DO8(o1a, f10, f11, f12, f13, p0, p1, p2, p3);
                }
                {   // output o+32 (high halves)
                    MK_PACKS(p0, p1, p2, p3, hhi(va.x), hhi(va.y), hhi(vb.x), hhi(vb.y), hhi(vc.x));
                    DO8(o0b, f00, f01, f02, f03, p0, p1, p2, p3);
                    DO8(o1b, f10, f11, f12, f13, p0, p1, p2, p3);
                }
            }
        }

        // ---- stores: natural blade order ----
        {
            float4* op0 = reinterpret_cast<float4*>(out + (size_t)tok0 * 1024);
            float4* op1 = reinterpret_cast<float4*>(out + (size_t)(tok0 + 1) * 1024);
            float v[16];
            UNPK(o0a, v);
            op0[lane * 4 + 0] = make_float4(v[0], v[1], v[2], v[3]);
            op0[lane * 4 + 1] = make_float4(v[4], v[5], v[6], v[7]);
            op0[lane * 4 + 2] = make_float4(v[8], v[9], v[10], v[11]);
            op0[lane * 4 + 3] = make_float4(v[12], v[13], v[14], v[15]);
            UNPK(o0b, v);
            op0[(lane + 32) * 4 + 0] = make_float4(v[0], v[1], v[2], v[3]);
            op0[(lane + 32) * 4 + 1] = make_float4(v[4], v[5], v[6], v[7]);
            op0[(lane + 32) * 4 + 2] = make_float4(v[8], v[9], v[10], v[11]);
            op0[(lane + 32) * 4 + 3] = make_float4(v[12], v[13], v[14], v[15]);
            UNPK(o1a, v);
            op1[lane * 4 + 0] = make_float4(v[0], v[1], v[2], v[3]);
            op1[lane * 4 + 1] = make_float4(v[4], v[5], v[6], v[7]);
            op1[lane * 4 + 2] = make_float4(v[8], v[9], v[10], v[11]);
            op1[lane * 4 + 3] = make_float4(v[12], v[13], v[14], v[15]);
            UNPK(o1b, v);
            op1[(lane + 32) * 4 + 0] = make_float4(v[0], v[1], v[2], v[3]);
            op1[(lane + 32) * 4 + 1] = make_float4(v[4], v[5], v[6], v[7]);
            op1[(lane + 32) * 4 + 2] = make_float4(v[8], v[9], v[10], v[11]);
            op1[(lane + 32) * 4 + 3] = make_float4(v[12], v[13], v[14], v[15]);
        }
        __syncwarp();   // feats reads done before next iteration's x overwrite
    }
}

// ---------------------------------------------------------------------------
extern "C" void kernel_launch(void* const* d_in, const int* in_sizes, int n_in,
                              void* d_out, int out_size) {
    const float* x   = (const float*)d_in[0];
    const float* ref = (const float*)d_in[1];
    const float* wpx = (const float*)d_in[2];
    const float* wpy = (const float*)d_in[3];
    const float* wjx = (const float*)d_in[4];
    const float* wjy = (const float*)d_in[5];
    const float* wf  = (const float*)d_in[6];
    float* out = (float*)d_out;

    prep_kernel<<<8, 256>>>(wpx, wpy, wjx, wjy, wf);

    cudaFuncSetAttribute(gbl_kernel, cudaFuncAttributeMaxDynamicSharedMemorySize, SMEM_BYTES);
    gbl_kernel<<<GRID, THREADS, SMEM_BYTES>>>(x, ref, out);
}